// round 9
// baseline (speedup 1.0000x reference)
#include <cuda_runtime.h>

#define NG 16
#define NC 8192
#define NCHUNK 32            // 8192 / 256
#define LATX 0.78125f
#define LATY 0.78125f
#define LATZ 0.375f
#define DIAM0 ((float)(0.74 * 1.4))
#define DIAM1 ((float)(0.528 * 1.4))
#define NCOLMAX 1089         // 33*33
#define CAP 32               // slots per (x,y) column bucket
#define NCOLCAP (NCOLMAX * CAP)
#define FULLM 0xffffffffu

// ---------------------------------------------------------------------------
// Global scratch
// ---------------------------------------------------------------------------
__device__ float4 g_pp4[NG][NC];     // compact preds (x,y,z,q)
__device__ float4 g_praw4[NG][NC];   // compact pred raw rows
__device__ unsigned long long g_key[NG][NC];
__device__ int g_pslot[NG][NC];      // col*CAP+slot of each compact pred
__device__ float4 g_tp4[NG][NC];     // compact targets (x,y,z,q)
__device__ float4 g_traw4[NG][NC];

__device__ int g_chunkP[NG][NCHUNK], g_chunkT[NG][NCHUNK];
__device__ int g_chunkBaseP[NG][NCHUNK], g_chunkBaseT[NG][NCHUNK];

// pred column buckets
__device__ float4 g_bp4[NG][NCOLCAP];
__device__ unsigned long long g_bkey[NG][NCOLCAP];
__device__ int g_borig[NG][NCOLCAP];
__device__ int g_bcnt[NG][NCOLMAX];          // zeroed each replay in k_count
__device__ unsigned char g_br0[NG][NCOLCAP];

__device__ unsigned long long g_kkey[NG][NC];
__device__ int g_nkc[NG];                    // reset each replay in k_scan2

// key-sorted kept + kept buckets
__device__ int g_nsrc[NG][NC];
__device__ float4 g_kp4r[NG][NC];
__device__ float4 g_kb4[NG][NCOLCAP];
__device__ int g_kbrk[NG][NCOLCAP];
__device__ int g_kbcnt[NG][NCOLMAX];         // zeroed each replay in k_res0

__device__ int g_m[NG][NC], g_piv[NG][NC], g_mn[NG][NC], g_pinv[NG][NC];
__device__ int g_ti[NG][NC], g_pi[NG][NC], g_tin[NG][NC], g_pin[NG][NC];
__device__ int g_np[NG], g_nt[NG], g_nn[NG], g_k[NG], g_kn[NG];

// ---------------------------------------------------------------------------
// Helpers
// ---------------------------------------------------------------------------
__device__ __forceinline__ void gdims2(int e, int& CX, int& CY) {
    if (e) { CX = 33; CY = 33; } else { CX = 24; CY = 24; }
}

__device__ __forceinline__ float sqnorm3(float x, float y, float z) {
    return __fadd_rn(__fadd_rn(__fmul_rn(x, x), __fmul_rn(y, y)), __fmul_rn(z, z));
}

__device__ __forceinline__ float dist2(float qi, float qj,
                                       float xi, float yi, float zi,
                                       float xj, float yj, float zj) {
    float ab = __fmul_rn(xi, xj);
    ab = fmaf(yi, yj, ab);
    ab = fmaf(zi, zj, ab);
    return __fsub_rn(__fadd_rn(qi, qj), __fmul_rn(2.0f, ab));
}

// smallest S with sqrtf(S) >= D (device-sqrt calibrated); then
// rn(sqrt(max(s,0))) < D  <=>  s < S
__device__ __forceinline__ float sqr_thresh(float D) {
    float s = __fmul_rn(D, D);
    while (sqrtf(s) < D) s = __uint_as_float(__float_as_uint(s) + 1u);
    for (;;) {
        float sm = __uint_as_float(__float_as_uint(s) - 1u);
        if (sqrtf(sm) >= D) s = sm; else break;
    }
    return s;
}

__device__ __forceinline__ int colOf(float x, float y, float fx, float fy,
                                     int CX, int CY) {
    int cx = min(max((int)(x * fx), 0), CX - 1);
    int cy = min(max((int)(y * fy), 0), CY - 1);
    return cx * CY + cy;
}

// ---------------------------------------------------------------------------
// K1 wide: chunk counts; also zero g_bcnt for this replay
// ---------------------------------------------------------------------------
__global__ void k_count(const float* __restrict__ pred,
                        const float* __restrict__ tgt) {
    int g = blockIdx.y, ch = blockIdx.x, tid = threadIdx.x;
    int b = g >> 1, e = g & 1;
    int cell = ch * 256 + tid;
    float4 pv = ((const float4*)pred)[(b * NC + cell) * 2 + e];
    float4 tv = ((const float4*)tgt)[(b * NC + cell) * 2 + e];
    int mp = pv.w > 0.5f;
    int mt = tv.w > 0.5f;
    if (ch == 0)
        for (int c = tid; c < NCOLMAX; c += 256) g_bcnt[g][c] = 0;
    int cp = __syncthreads_count(mp);
    int ct = __syncthreads_count(mt);
    if (tid == 0) { g_chunkP[g][ch] = cp; g_chunkT[g][ch] = ct; }
}

// ---------------------------------------------------------------------------
// K2 (1 block x 1024): chunk scans (warp per group/kind) + resets
// ---------------------------------------------------------------------------
__global__ void k_scan2() {
    int tid = threadIdx.x, lane = tid & 31, w = tid >> 5;
    if (w < NG) {
        int g = w;
        int v = g_chunkP[g][lane];
        int incl = v;
        #pragma unroll
        for (int o = 1; o < 32; o <<= 1) { int t = __shfl_up_sync(FULLM, incl, o); if (lane >= o) incl += t; }
        g_chunkBaseP[g][lane] = incl - v;
        if (lane == 31) g_np[g] = incl;
        if (lane == 0) g_nkc[g] = 0;
    } else {
        int g = w - NG;
        int v = g_chunkT[g][lane];
        int incl = v;
        #pragma unroll
        for (int o = 1; o < 32; o <<= 1) { int t = __shfl_up_sync(FULLM, incl, o); if (lane >= o) incl += t; }
        g_chunkBaseT[g][lane] = incl - v;
        if (lane == 31) g_nt[g] = incl;
    }
}

// ---------------------------------------------------------------------------
// K3 wide: scatter compact arrays + column buckets (global atomic slot grab)
// ---------------------------------------------------------------------------
__global__ void k_scatter(const float* __restrict__ pred,
                          const float* __restrict__ tgt) {
    int g = blockIdx.y, ch = blockIdx.x, tid = threadIdx.x;
    int lane = tid & 31, wid = tid >> 5;
    int b = g >> 1, e = g & 1;
    int CX, CY; gdims2(e, CX, CY);
    float fx = CX / 25.0f, fy = CY / 25.0f;
    __shared__ int s_w1[8], s_w2[8];

    int cell = ch * 256 + tid;
    int i = cell >> 8, j = (cell >> 3) & 31, k = cell & 7;
    float4 pv = ((const float4*)pred)[(b * NC + cell) * 2 + e];
    float4 tv = ((const float4*)tgt)[(b * NC + cell) * 2 + e];
    int mp = pv.w > 0.5f;
    int mt = tv.w > 0.5f;

    unsigned bp = __ballot_sync(FULLM, mp);
    unsigned bt = __ballot_sync(FULLM, mt);
    if (lane == 0) { s_w1[wid] = __popc(bp); s_w2[wid] = __popc(bt); }
    __syncthreads();
    int offp = g_chunkBaseP[g][ch], offt = g_chunkBaseT[g][ch];
    for (int x = 0; x < wid; x++) { offp += s_w1[x]; offt += s_w2[x]; }
    offp += __popc(bp & ((1u << lane) - 1u));
    offt += __popc(bt & ((1u << lane) - 1u));

    if (mp) {
        float px = __fmul_rn(__fadd_rn(pv.x, (float)i), LATX);
        float py = __fmul_rn(__fadd_rn(pv.y, (float)j), LATY);
        float pz = __fmul_rn(__fadd_rn(pv.z, (float)k), LATZ);
        float q = sqnorm3(px, py, pz);
        float4 pos4 = make_float4(px, py, pz, q);
        unsigned long long key =
            ((unsigned long long)__float_as_uint(pv.w) << 32) | (unsigned)offp;
        g_praw4[g][offp] = pv;
        g_pp4[g][offp] = pos4;
        g_key[g][offp] = key;
        int col = colOf(px, py, fx, fy, CX, CY);
        int slot = atomicAdd(&g_bcnt[g][col], 1);
        slot = min(slot, CAP - 1);
        int bi = col * CAP + slot;
        g_bp4[g][bi] = pos4;
        g_bkey[g][bi] = key;
        g_borig[g][bi] = offp;
        g_pslot[g][offp] = bi;
    }
    if (mt) {
        float tx = __fmul_rn(__fadd_rn(tv.x, (float)i), LATX);
        float ty = __fmul_rn(__fadd_rn(tv.y, (float)j), LATY);
        float tz = __fmul_rn(__fadd_rn(tv.z, (float)k), LATZ);
        g_traw4[g][offt] = tv;
        g_tp4[g][offt] = make_float4(tx, ty, tz, sqnorm3(tx, ty, tz));
    }
}

// ---------------------------------------------------------------------------
// K4/K5 wide: restrain==0 / sel flags via 3x3 column scan
// ---------------------------------------------------------------------------
template<int CHECK_R0>
__device__ __forceinline__ int flagScan(int g, int jj, int CX, int CY, float S2) {
    float4 P = g_pp4[g][jj];
    unsigned long long kj = g_key[g][jj];
    int ps = g_pslot[g][jj];
    int col = ps / CAP;
    int cx = col / CY, cy = col % CY;
    int x0 = max(cx - 1, 0), x1 = min(cx + 1, CX - 1);
    int y0 = max(cy - 1, 0), y1 = min(cy + 1, CY - 1);
    int ok = 1;
    for (int ax = x0; ax <= x1 && ok; ax++)
    for (int ay = y0; ay <= y1 && ok; ay++) {
        int c0 = ax * CY + ay;
        int n = min(g_bcnt[g][c0], CAP);
        int base = c0 * CAP;
        for (int s = 0; s < n; s++) {
            if (CHECK_R0 && !g_br0[g][base + s]) continue;
            if (g_bkey[g][base + s] < kj) {
                float4 C = g_bp4[g][base + s];
                float s2 = dist2(C.w, P.w, C.x, C.y, C.z, P.x, P.y, P.z);
                if (s2 < S2) { ok = 0; break; }
            }
        }
    }
    return ok;
}

__global__ void k_res0() {
    int g = blockIdx.y;
    int jj = blockIdx.x * blockDim.x + threadIdx.x;
    // zero kept-bucket counters for this replay (before k_rank's atomics)
    if (blockIdx.x == 0)
        for (int c = threadIdx.x; c < NCOLMAX; c += 256) g_kbcnt[g][c] = 0;
    if (jj >= g_np[g]) return;
    int e = g & 1;
    int CX, CY; gdims2(e, CX, CY);
    float S2 = sqr_thresh(e ? DIAM1 : DIAM0);
    g_br0[g][g_pslot[g][jj]] = (unsigned char)flagScan<0>(g, jj, CX, CY, S2);
}

__global__ void k_sel() {
    int g = blockIdx.y;
    int jj = blockIdx.x * blockDim.x + threadIdx.x;
    int lane = threadIdx.x & 31;
    int e = g & 1;
    int CX, CY; gdims2(e, CX, CY);
    float S2 = sqr_thresh(e ? DIAM1 : DIAM0);
    int keep = 0;
    if (jj < g_np[g]) keep = flagScan<1>(g, jj, CX, CY, S2);
    unsigned m = __ballot_sync(FULLM, keep);
    if (m) {
        int base;
        if (lane == __ffs(m) - 1) base = atomicAdd(&g_nkc[g], __popc(m));
        base = __shfl_sync(FULLM, base, __ffs(m) - 1);
        if (keep) g_kkey[g][base + __popc(m & ((1u << lane) - 1u))] = g_key[g][jj];
    }
}

// ---------------------------------------------------------------------------
// K6 wide: rank-count sort of kept keys + gather + kept buckets
// ---------------------------------------------------------------------------
__global__ void k_rank() {
    int g = blockIdx.y;
    int i = blockIdx.x * blockDim.x + threadIdx.x;
    int e = g & 1;
    int CX, CY; gdims2(e, CX, CY);
    float fx = CX / 25.0f, fy = CY / 25.0f;
    int nk = g_nkc[g];
    if (i == 0) g_nn[g] = nk;
    if (i >= nk) return;
    unsigned long long ki = g_kkey[g][i];
    int rank = 0;
    for (int j = 0; j < nk; j++) rank += (g_kkey[g][j] < ki);
    int src = (int)(ki & 0xffffffffull);
    g_nsrc[g][rank] = src;
    float4 P = g_pp4[g][src];
    g_kp4r[g][rank] = P;
    int col = colOf(P.x, P.y, fx, fy, CX, CY);
    int slot = atomicAdd(&g_kbcnt[g][col], 1);
    slot = min(slot, CAP - 1);
    int bi = col * CAP + slot;
    g_kb4[g][bi] = P;
    g_kbrk[g][bi] = rank;
}

// ---------------------------------------------------------------------------
// K7 wide: match targets vs pred buckets and kept buckets
// ---------------------------------------------------------------------------
__global__ void k_match() {
    int g = blockIdx.y;
    int t = blockIdx.x * blockDim.x + threadIdx.x;
    if (t >= g_nt[g]) return;
    int e = g & 1;
    int CX, CY; gdims2(e, CX, CY);
    float S2 = sqr_thresh(e ? DIAM1 : DIAM0);
    float fx = CX / 25.0f, fy = CY / 25.0f;
    float4 T = g_tp4[g][t];
    int col = colOf(T.x, T.y, fx, fy, CX, CY);
    int cx = col / CY, cy = col % CY;
    int x0 = max(cx - 1, 0), x1 = min(cx + 1, CX - 1);
    int y0 = max(cy - 1, 0), y1 = min(cy + 1, CY - 1);

    {
        int any = 0; float bs = __int_as_float(0x7f800000); int bi = 0x7fffffff;
        for (int ax = x0; ax <= x1; ax++)
        for (int ay = y0; ay <= y1; ay++) {
            int c0 = ax * CY + ay;
            int n = min(g_bcnt[g][c0], CAP);
            int base = c0 * CAP;
            for (int sI = 0; sI < n; sI++) {
                float4 C = g_bp4[g][base + sI];
                float s = dist2(T.w, C.w, T.x, T.y, T.z, C.x, C.y, C.z);
                s = fmaxf(s, 0.0f);
                int jj = g_borig[g][base + sI];
                any |= (s < S2);
                if (s < bs) {
                    bi = (sqrtf(s) == sqrtf(bs)) ? min(bi, jj) : jj;
                    bs = s;
                } else if (jj < bi && s <= __fmul_rn(bs, 1.000001f)) {
                    if (sqrtf(s) == sqrtf(bs)) bi = jj;
                }
            }
        }
        g_m[g][t] = any; g_piv[g][t] = (bi == 0x7fffffff) ? 0 : bi;
    }
    {
        int any = 0; float bs = __int_as_float(0x7f800000); int bi = 0x7fffffff;
        for (int ax = x0; ax <= x1; ax++)
        for (int ay = y0; ay <= y1; ay++) {
            int c0 = ax * CY + ay;
            int n = min(g_kbcnt[g][c0], CAP);
            int base = c0 * CAP;
            for (int sI = 0; sI < n; sI++) {
                float4 C = g_kb4[g][base + sI];
                float s = dist2(T.w, C.w, T.x, T.y, T.z, C.x, C.y, C.z);
                s = fmaxf(s, 0.0f);
                int jj = g_kbrk[g][base + sI];
                any |= (s < S2);
                if (s < bs) {
                    bi = (sqrtf(s) == sqrtf(bs)) ? min(bi, jj) : jj;
                    bs = s;
                } else if (jj < bi && s <= __fmul_rn(bs, 1.000001f)) {
                    if (sqrtf(s) == sqrtf(bs)) bi = jj;
                }
            }
        }
        g_mn[g][t] = any; g_pinv[g][t] = (bi == 0x7fffffff) ? 0 : bi;
    }
}

// ---------------------------------------------------------------------------
// K8 (16 blocks x 1024): compact matches (stable)
// ---------------------------------------------------------------------------
__global__ void __launch_bounds__(1024, 1) k_post() {
    int g = blockIdx.x;
    int tid = threadIdx.x;
    int lane = tid & 31, w = tid >> 5;
    int Nt = g_nt[g];
    __shared__ int wt[32];
    __shared__ int base;

    for (int pass = 0; pass < 2; pass++) {
        if (tid == 0) base = 0;
        __syncthreads();
        for (int cb = 0; cb < Nt; cb += 1024) {
            int t = cb + tid;
            int f = 0;
            if (t < Nt) f = pass ? g_mn[g][t] : g_m[g][t];
            unsigned bl = __ballot_sync(FULLM, f != 0);
            if (lane == 0) wt[w] = __popc(bl);
            __syncthreads();
            int off = base;
            for (int x = 0; x < w; x++) off += wt[x];
            off += __popc(bl & ((1u << lane) - 1u));
            if (f) {
                if (pass) { g_tin[g][off] = t; g_pin[g][off] = g_pinv[g][t]; }
                else      { g_ti[g][off]  = t; g_pi[g][off]  = g_piv[g][t]; }
            }
            __syncthreads();
            if (tid == 0) { int s = 0; for (int x = 0; x < 32; x++) s += wt[x]; base += s; }
            __syncthreads();
        }
        if (tid == 0) { if (pass) g_kn[g] = base; else g_k[g] = base; }
        __syncthreads();
    }
}

// ---------------------------------------------------------------------------
// K9 wide: write output
// ---------------------------------------------------------------------------
__global__ void k_write(float* __restrict__ out) {
    int g = blockIdx.y;
    __shared__ long long s_base;
    __shared__ int s_sz[5];
    if (threadIdx.x == 0) {
        long long base = 0;
        for (int g2 = 0; g2 < g; g2++) {
            long long Np = g_np[g2], Nn = g_nn[g2], Nt = g_nt[g2];
            long long K = g_k[g2], Kn = g_kn[g2];
            base += Np * 7 + Nn * 7 + Nt * 7 + 2 * K + 2 * Kn;
        }
        s_base = base;
        s_sz[0] = g_np[g]; s_sz[1] = g_nn[g]; s_sz[2] = g_nt[g];
        s_sz[3] = g_k[g];  s_sz[4] = g_kn[g];
    }
    __syncthreads();
    long long base = s_base;
    int Np = s_sz[0], Nn = s_sz[1], Nt = s_sz[2], K = s_sz[3], Kn = s_sz[4];
    int T = Np * 7 + Nn * 7 + Nt * 7 + 2 * K + 2 * Kn;
    const float* praw = (const float*)g_praw4[g];
    const float* traw = (const float*)g_traw4[g];
    const float* pp = (const float*)g_pp4[g];
    const float* tp = (const float*)g_tp4[g];
    const float* kp = (const float*)g_kp4r[g];
    int stride = gridDim.x * blockDim.x;
    for (int idx = blockIdx.x * blockDim.x + threadIdx.x; idx < T; idx += stride) {
        int o = idx;
        float v;
        if (o < Np * 4) { v = praw[o]; }
        else {
            o -= Np * 4;
            if (o < Nn * 4) { v = praw[g_nsrc[g][o >> 2] * 4 + (o & 3)]; }
            else {
                o -= Nn * 4;
                if (o < Nt * 4) { v = traw[o]; }
                else {
                    o -= Nt * 4;
                    if (o < K) { v = (float)g_ti[g][o]; }
                    else {
                        o -= K;
                        if (o < K) { v = (float)g_pi[g][o]; }
                        else {
                            o -= K;
                            if (o < Kn) { v = (float)g_tin[g][o]; }
                            else {
                                o -= Kn;
                                if (o < Kn) { v = (float)g_pin[g][o]; }
                                else {
                                    o -= Kn;
                                    if (o < Np * 3) { v = pp[(o / 3) * 4 + o % 3]; }
                                    else {
                                        o -= Np * 3;
                                        if (o < Nn * 3) { v = kp[(o / 3) * 4 + o % 3]; }
                                        else { o -= Nn * 3; v = tp[(o / 3) * 4 + o % 3]; }
                                    }
                                }
                            }
                        }
                    }
                }
            }
        }
        out[base + idx] = v;
    }
}

// ---------------------------------------------------------------------------
// launch: 9 graph nodes, all wide except k_scan2 (1 block) and k_post
// ---------------------------------------------------------------------------
extern "C" void kernel_launch(void* const* d_in, const int* in_sizes, int n_in,
                              void* d_out, int out_size) {
    const float* pred = (const float*)d_in[0];
    const float* tgt  = (const float*)d_in[1];
    float* out = (float*)d_out;
    (void)in_sizes; (void)n_in; (void)out_size;

    dim3 wide(NCHUNK, NG);
    k_count<<<wide, 256>>>(pred, tgt);
    k_scan2<<<1, 1024>>>();
    k_scatter<<<wide, 256>>>(pred, tgt);
    k_res0<<<wide, 256>>>();
    k_sel<<<wide, 256>>>();
    k_rank<<<wide, 256>>>();
    k_match<<<wide, 256>>>();
    k_post<<<NG, 1024>>>();
    k_write<<<wide, 256>>>(out);
}

// round 10
// speedup vs baseline: 1.0233x; 1.0233x over previous
#include <cuda_runtime.h>

#define NG 16
#define NC 8192
#define NCHUNK 32            // 8192 / 256
#define LATX 0.78125f
#define LATY 0.78125f
#define LATZ 0.375f
#define DIAM0 ((float)(0.74 * 1.4))
#define DIAM1 ((float)(0.528 * 1.4))
#define MAXCELLS 4608        // >= 33*33*4
#define NCOLMAX 1089         // 33*33 (kept-side buckets)
#define CAP 32
#define NCOLCAP (NCOLMAX * CAP)
#define FULLM 0xffffffffu

// ---------------------------------------------------------------------------
// Global scratch
// ---------------------------------------------------------------------------
__device__ float4 g_pp4[NG][NC];     // compact preds (x,y,z,q)
__device__ float4 g_praw4[NG][NC];
__device__ unsigned long long g_key[NG][NC];
__device__ float4 g_tp4[NG][NC];
__device__ float4 g_traw4[NG][NC];

__device__ int g_chunkP[NG][NCHUNK], g_chunkT[NG][NCHUNK];
__device__ int g_chunkBaseP[NG][NCHUNK], g_chunkBaseT[NG][NCHUNK];
__device__ int g_ccnt[NG][MAXCELLS];          // zero invariant (k_scan re-zeros)
__device__ int g_cstart[NG][MAXCELLS + 1];
__device__ int g_cellfill[NG][MAXCELLS];

// cell-sorted pred SoA (contiguous ranges, z-collapsed scan)
__device__ float4 g_s4[NG][NC];               // (x,y,z,q)
__device__ unsigned long long g_skey[NG][NC];
__device__ int g_sorig[NG][NC], g_scell[NG][NC];
__device__ unsigned char g_r0s[NG][NC];

__device__ unsigned long long g_kkey[NG][NC];
__device__ int g_nkc[NG];                     // reset in k_scan

// key-sorted kept + kept column buckets
__device__ int g_nsrc[NG][NC];
__device__ float4 g_kp4r[NG][NC];
__device__ float4 g_kb4[NG][NCOLCAP];
__device__ int g_kbrk[NG][NCOLCAP];
__device__ int g_kbcnt[NG][NCOLMAX];          // zeroed in k_res0 each replay

__device__ int g_m[NG][NC], g_piv[NG][NC], g_mn[NG][NC], g_pinv[NG][NC];
__device__ int g_ti[NG][NC], g_pi[NG][NC], g_tin[NG][NC], g_pin[NG][NC];
__device__ int g_np[NG], g_nt[NG], g_nn[NG], g_k[NG], g_kn[NG];

// ---------------------------------------------------------------------------
// Helpers
// ---------------------------------------------------------------------------
__device__ __forceinline__ void gdims(int e, int& CX, int& CY, int& CZ) {
    if (e) { CX = 33; CY = 33; CZ = 4; } else { CX = 24; CY = 24; CZ = 2; }
}

__device__ __forceinline__ float sqnorm3(float x, float y, float z) {
    return __fadd_rn(__fadd_rn(__fmul_rn(x, x), __fmul_rn(y, y)), __fmul_rn(z, z));
}

__device__ __forceinline__ float dist2(float qi, float qj,
                                       float xi, float yi, float zi,
                                       float xj, float yj, float zj) {
    float ab = __fmul_rn(xi, xj);
    ab = fmaf(yi, yj, ab);
    ab = fmaf(zi, zj, ab);
    return __fsub_rn(__fadd_rn(qi, qj), __fmul_rn(2.0f, ab));
}

// smallest S with sqrtf(S) >= D (device-sqrt calibrated)
__device__ __forceinline__ float sqr_thresh(float D) {
    float s = __fmul_rn(D, D);
    while (sqrtf(s) < D) s = __uint_as_float(__float_as_uint(s) + 1u);
    for (;;) {
        float sm = __uint_as_float(__float_as_uint(s) - 1u);
        if (sqrtf(sm) >= D) s = sm; else break;
    }
    return s;
}

__device__ __forceinline__ int cellOf(float x, float y, float z,
                                      float fx, float fy, float fz,
                                      int CX, int CY, int CZ) {
    int cx = min(max((int)(x * fx), 0), CX - 1);
    int cy = min(max((int)(y * fy), 0), CY - 1);
    int cz = min(max((int)(z * fz), 0), CZ - 1);
    return (cx * CY + cy) * CZ + cz;
}

// ---------------------------------------------------------------------------
// K1 wide: chunk counts + cell histogram
// ---------------------------------------------------------------------------
__global__ void k_count(const float* __restrict__ pred,
                        const float* __restrict__ tgt) {
    int g = blockIdx.y, ch = blockIdx.x, tid = threadIdx.x;
    int b = g >> 1, e = g & 1;
    int CX, CY, CZ; gdims(e, CX, CY, CZ);
    float fx = CX / 25.0f, fy = CY / 25.0f, fz = CZ / 3.0f;

    int cell = ch * 256 + tid;
    int i = cell >> 8, j = (cell >> 3) & 31, k = cell & 7;
    float4 pv = ((const float4*)pred)[(b * NC + cell) * 2 + e];
    float4 tv = ((const float4*)tgt)[(b * NC + cell) * 2 + e];
    int mp = pv.w > 0.5f;
    int mt = tv.w > 0.5f;

    if (mp) {
        float px = __fmul_rn(__fadd_rn(pv.x, (float)i), LATX);
        float py = __fmul_rn(__fadd_rn(pv.y, (float)j), LATY);
        float pz = __fmul_rn(__fadd_rn(pv.z, (float)k), LATZ);
        atomicAdd(&g_ccnt[g][cellOf(px, py, pz, fx, fy, fz, CX, CY, CZ)], 1);
    }
    int cp = __syncthreads_count(mp);
    int ct = __syncthreads_count(mt);
    if (tid == 0) { g_chunkP[g][ch] = cp; g_chunkT[g][ch] = ct; }
}

// ---------------------------------------------------------------------------
// K2 (NG blocks x 1024): scans + resets
// ---------------------------------------------------------------------------
__global__ void __launch_bounds__(1024, 1) k_scan() {
    int g = blockIdx.x, tid = threadIdx.x, lane = tid & 31, wid = tid >> 5;
    int e = g & 1;
    int CX, CY, CZ; gdims(e, CX, CY, CZ);
    int NCELL = CX * CY * CZ;
    __shared__ int s_warpsum[32];

    if (tid == 0) {
        int rp = 0, rt = 0;
        for (int c = 0; c < NCHUNK; c++) {
            g_chunkBaseP[g][c] = rp; rp += g_chunkP[g][c];
            g_chunkBaseT[g][c] = rt; rt += g_chunkT[g][c];
        }
        g_np[g] = rp; g_nt[g] = rt;
        g_nkc[g] = 0;
    }

    const int CH = 5;
    int lo = tid * CH, hi = min(lo + CH, NCELL);
    int acc = 0;
    for (int c = lo; c < hi; c++) acc += g_ccnt[g][c];
    int v = acc;
    #pragma unroll
    for (int o = 1; o < 32; o <<= 1) { int t = __shfl_up_sync(FULLM, v, o); if (lane >= o) v += t; }
    if (lane == 31) s_warpsum[wid] = v;
    __syncthreads();
    if (wid == 0) {
        int wv = s_warpsum[lane];
        int w2 = wv;
        #pragma unroll
        for (int o = 1; o < 32; o <<= 1) { int t = __shfl_up_sync(FULLM, w2, o); if (lane >= o) w2 += t; }
        s_warpsum[lane] = w2 - wv;
    }
    __syncthreads();
    int run = (v - acc) + s_warpsum[wid];
    for (int c = lo; c < hi; c++) {
        int t = g_ccnt[g][c];
        g_cstart[g][c] = run;
        g_cellfill[g][c] = run;
        g_ccnt[g][c] = 0;            // zero-after-use for next replay
        run += t;
    }
    if (hi == NCELL && lo < NCELL) g_cstart[g][NCELL] = run;  // unique writer
}

// ---------------------------------------------------------------------------
// K3 wide: scatter compacted arrays + cell-sorted float4 SoA
// ---------------------------------------------------------------------------
__global__ void k_scatter(const float* __restrict__ pred,
                          const float* __restrict__ tgt) {
    int g = blockIdx.y, ch = blockIdx.x, tid = threadIdx.x;
    int lane = tid & 31, wid = tid >> 5;
    int b = g >> 1, e = g & 1;
    int CX, CY, CZ; gdims(e, CX, CY, CZ);
    float fx = CX / 25.0f, fy = CY / 25.0f, fz = CZ / 3.0f;
    __shared__ int s_w1[8], s_w2[8];

    int cell = ch * 256 + tid;
    int i = cell >> 8, j = (cell >> 3) & 31, k = cell & 7;
    float4 pv = ((const float4*)pred)[(b * NC + cell) * 2 + e];
    float4 tv = ((const float4*)tgt)[(b * NC + cell) * 2 + e];
    int mp = pv.w > 0.5f;
    int mt = tv.w > 0.5f;

    unsigned bp = __ballot_sync(FULLM, mp);
    unsigned bt = __ballot_sync(FULLM, mt);
    if (lane == 0) { s_w1[wid] = __popc(bp); s_w2[wid] = __popc(bt); }
    __syncthreads();
    int offp = g_chunkBaseP[g][ch], offt = g_chunkBaseT[g][ch];
    for (int x = 0; x < wid; x++) { offp += s_w1[x]; offt += s_w2[x]; }
    offp += __popc(bp & ((1u << lane) - 1u));
    offt += __popc(bt & ((1u << lane) - 1u));

    if (mp) {
        float px = __fmul_rn(__fadd_rn(pv.x, (float)i), LATX);
        float py = __fmul_rn(__fadd_rn(pv.y, (float)j), LATY);
        float pz = __fmul_rn(__fadd_rn(pv.z, (float)k), LATZ);
        float q = sqnorm3(px, py, pz);
        float4 pos4 = make_float4(px, py, pz, q);
        unsigned long long key =
            ((unsigned long long)__float_as_uint(pv.w) << 32) | (unsigned)offp;
        g_praw4[g][offp] = pv;
        g_pp4[g][offp] = pos4;
        g_key[g][offp] = key;
        int c = cellOf(px, py, pz, fx, fy, fz, CX, CY, CZ);
        int p = atomicAdd(&g_cellfill[g][c], 1);
        g_s4[g][p] = pos4;
        g_skey[g][p] = key;
        g_sorig[g][p] = offp;
        g_scell[g][p] = c;
    }
    if (mt) {
        float tx = __fmul_rn(__fadd_rn(tv.x, (float)i), LATX);
        float ty = __fmul_rn(__fadd_rn(tv.y, (float)j), LATY);
        float tz = __fmul_rn(__fadd_rn(tv.z, (float)k), LATZ);
        g_traw4[g][offt] = tv;
        g_tp4[g][offt] = make_float4(tx, ty, tz, sqnorm3(tx, ty, tz));
    }
}

// ---------------------------------------------------------------------------
// K4/K5 wide: restrain==0 / sel flags (z-collapsed ranges, float4 loads)
// ---------------------------------------------------------------------------
template<int CHECK_R0>
__device__ __forceinline__ int flagScan(int g, int jj, int CX, int CY, int CZ, float S2) {
    float4 P = g_s4[g][jj];
    unsigned long long kj = g_skey[g][jj];
    int c = g_scell[g][jj];
    int cz = c % CZ, cy = (c / CZ) % CY, cx = c / (CZ * CY);
    int z0 = max(cz - 1, 0), z1 = min(cz + 1, CZ - 1);
    int ok = 1;
    for (int ax = max(cx - 1, 0); ax <= min(cx + 1, CX - 1) && ok; ax++)
    for (int ay = max(cy - 1, 0); ay <= min(cy + 1, CY - 1) && ok; ay++) {
        int rowc = (ax * CY + ay) * CZ;
        int p1 = g_cstart[g][rowc + z1 + 1];
        for (int p = g_cstart[g][rowc + z0]; p < p1; p++) {
            if (CHECK_R0 && !g_r0s[g][p]) continue;
            if (g_skey[g][p] < kj) {
                float4 C = g_s4[g][p];
                float s = dist2(C.w, P.w, C.x, C.y, C.z, P.x, P.y, P.z);
                if (s < S2) { ok = 0; break; }
            }
        }
    }
    return ok;
}

__global__ void k_res0() {
    int g = blockIdx.y;
    int jj = blockIdx.x * blockDim.x + threadIdx.x;
    // zero kept-bucket counters for this replay (consumed by k_rank later)
    if (blockIdx.x == 0)
        for (int c = threadIdx.x; c < NCOLMAX; c += 256) g_kbcnt[g][c] = 0;
    if (jj >= g_np[g]) return;
    int e = g & 1;
    int CX, CY, CZ; gdims(e, CX, CY, CZ);
    float S2 = sqr_thresh(e ? DIAM1 : DIAM0);
    g_r0s[g][jj] = (unsigned char)flagScan<0>(g, jj, CX, CY, CZ, S2);
}

__global__ void k_sel() {
    int g = blockIdx.y;
    int jj = blockIdx.x * blockDim.x + threadIdx.x;
    int lane = threadIdx.x & 31;
    int e = g & 1;
    int CX, CY, CZ; gdims(e, CX, CY, CZ);
    float S2 = sqr_thresh(e ? DIAM1 : DIAM0);
    int keep = 0;
    if (jj < g_np[g]) keep = flagScan<1>(g, jj, CX, CY, CZ, S2);
    unsigned m = __ballot_sync(FULLM, keep);
    if (m) {
        int base;
        int leader = __ffs(m) - 1;
        if (lane == leader) base = atomicAdd(&g_nkc[g], __popc(m));
        base = __shfl_sync(FULLM, base, leader);
        if (keep) g_kkey[g][base + __popc(m & ((1u << lane) - 1u))] = g_skey[g][jj];
    }
}

// ---------------------------------------------------------------------------
// K6 wide: rank-count sort of kept keys + gather + kept column buckets
// ---------------------------------------------------------------------------
__global__ void k_rank() {
    int g = blockIdx.y;
    int i = blockIdx.x * blockDim.x + threadIdx.x;
    int e = g & 1;
    int CX, CY, CZ; gdims(e, CX, CY, CZ);
    float fx = CX / 25.0f, fy = CY / 25.0f;
    int nk = g_nkc[g];
    if (i == 0) g_nn[g] = nk;
    if (i >= nk) return;
    unsigned long long ki = g_kkey[g][i];
    int rank = 0;
    for (int j = 0; j < nk; j++) rank += (g_kkey[g][j] < ki);
    int src = (int)(ki & 0xffffffffull);
    g_nsrc[g][rank] = src;
    float4 P = g_pp4[g][src];
    g_kp4r[g][rank] = P;
    int cx = min(max((int)(P.x * fx), 0), CX - 1);
    int cy = min(max((int)(P.y * fy), 0), CY - 1);
    int col = cx * CY + cy;
    int slot = atomicAdd(&g_kbcnt[g][col], 1);
    slot = min(slot, CAP - 1);
    int bi = col * CAP + slot;
    g_kb4[g][bi] = P;
    g_kbrk[g][bi] = rank;
}

// ---------------------------------------------------------------------------
// K7 wide: match (pred via cell ranges, kept via column buckets)
// ---------------------------------------------------------------------------
__global__ void k_match() {
    int g = blockIdx.y;
    int t = blockIdx.x * blockDim.x + threadIdx.x;
    if (t >= g_nt[g]) return;
    int e = g & 1;
    int CX, CY, CZ; gdims(e, CX, CY, CZ);
    float S2 = sqr_thresh(e ? DIAM1 : DIAM0);
    float fx = CX / 25.0f, fy = CY / 25.0f, fz = CZ / 3.0f;
    float4 T = g_tp4[g][t];
    int cx = min(max((int)(T.x * fx), 0), CX - 1);
    int cy = min(max((int)(T.y * fy), 0), CY - 1);
    int cz = min(max((int)(T.z * fz), 0), CZ - 1);
    int z0 = max(cz - 1, 0), z1 = min(cz + 1, CZ - 1);
    int x0 = max(cx - 1, 0), x1 = min(cx + 1, CX - 1);
    int y0 = max(cy - 1, 0), y1 = min(cy + 1, CY - 1);

    {
        int any = 0; float bs = __int_as_float(0x7f800000); int bi = 0x7fffffff;
        for (int ax = x0; ax <= x1; ax++)
        for (int ay = y0; ay <= y1; ay++) {
            int rowc = (ax * CY + ay) * CZ;
            int p1 = g_cstart[g][rowc + z1 + 1];
            for (int p = g_cstart[g][rowc + z0]; p < p1; p++) {
                float4 C = g_s4[g][p];
                float s = dist2(T.w, C.w, T.x, T.y, T.z, C.x, C.y, C.z);
                s = fmaxf(s, 0.0f);
                int jj = g_sorig[g][p];
                any |= (s < S2);
                if (s < bs) {
                    bi = (sqrtf(s) == sqrtf(bs)) ? min(bi, jj) : jj;
                    bs = s;
                } else if (jj < bi && s <= __fmul_rn(bs, 1.000001f)) {
                    if (sqrtf(s) == sqrtf(bs)) bi = jj;
                }
            }
        }
        g_m[g][t] = any; g_piv[g][t] = (bi == 0x7fffffff) ? 0 : bi;
    }
    {
        int any = 0; float bs = __int_as_float(0x7f800000); int bi = 0x7fffffff;
        for (int ax = x0; ax <= x1; ax++)
        for (int ay = y0; ay <= y1; ay++) {
            int c0 = ax * CY + ay;
            int n = min(g_kbcnt[g][c0], CAP);
            int base = c0 * CAP;
            for (int sI = 0; sI < n; sI++) {
                float4 C = g_kb4[g][base + sI];
                float s = dist2(T.w, C.w, T.x, T.y, T.z, C.x, C.y, C.z);
                s = fmaxf(s, 0.0f);
                int jj = g_kbrk[g][base + sI];
                any |= (s < S2);
                if (s < bs) {
                    bi = (sqrtf(s) == sqrtf(bs)) ? min(bi, jj) : jj;
                    bs = s;
                } else if (jj < bi && s <= __fmul_rn(bs, 1.000001f)) {
                    if (sqrtf(s) == sqrtf(bs)) bi = jj;
                }
            }
        }
        g_mn[g][t] = any; g_pinv[g][t] = (bi == 0x7fffffff) ? 0 : bi;
    }
}

// ---------------------------------------------------------------------------
// K8 (NG blocks x 1024): compact matches (stable)
// ---------------------------------------------------------------------------
__global__ void __launch_bounds__(1024, 1) k_post() {
    int g = blockIdx.x;
    int tid = threadIdx.x;
    int lane = tid & 31, w = tid >> 5;
    int Nt = g_nt[g];
    __shared__ int wt[32];
    __shared__ int base;

    for (int pass = 0; pass < 2; pass++) {
        if (tid == 0) base = 0;
        __syncthreads();
        for (int cb = 0; cb < Nt; cb += 1024) {
            int t = cb + tid;
            int f = 0;
            if (t < Nt) f = pass ? g_mn[g][t] : g_m[g][t];
            unsigned bl = __ballot_sync(FULLM, f != 0);
            if (lane == 0) wt[w] = __popc(bl);
            __syncthreads();
            int off = base;
            for (int x = 0; x < w; x++) off += wt[x];
            off += __popc(bl & ((1u << lane) - 1u));
            if (f) {
                if (pass) { g_tin[g][off] = t; g_pin[g][off] = g_pinv[g][t]; }
                else      { g_ti[g][off]  = t; g_pi[g][off]  = g_piv[g][t]; }
            }
            __syncthreads();
            if (tid == 0) { int s = 0; for (int x = 0; x < 32; x++) s += wt[x]; base += s; }
            __syncthreads();
        }
        if (tid == 0) { if (pass) g_kn[g] = base; else g_k[g] = base; }
        __syncthreads();
    }
}

// ---------------------------------------------------------------------------
// K9 wide: write output
// ---------------------------------------------------------------------------
__global__ void k_write(float* __restrict__ out) {
    int g = blockIdx.y;
    __shared__ long long s_base;
    __shared__ int s_sz[5];
    if (threadIdx.x == 0) {
        long long base = 0;
        for (int g2 = 0; g2 < g; g2++) {
            long long Np = g_np[g2], Nn = g_nn[g2], Nt = g_nt[g2];
            long long K = g_k[g2], Kn = g_kn[g2];
            base += Np * 7 + Nn * 7 + Nt * 7 + 2 * K + 2 * Kn;
        }
        s_base = base;
        s_sz[0] = g_np[g]; s_sz[1] = g_nn[g]; s_sz[2] = g_nt[g];
        s_sz[3] = g_k[g];  s_sz[4] = g_kn[g];
    }
    __syncthreads();
    long long base = s_base;
    int Np = s_sz[0], Nn = s_sz[1], Nt = s_sz[2], K = s_sz[3], Kn = s_sz[4];
    int T = Np * 7 + Nn * 7 + Nt * 7 + 2 * K + 2 * Kn;
    const float* praw = (const float*)g_praw4[g];
    const float* traw = (const float*)g_traw4[g];
    const float* pp = (const float*)g_pp4[g];
    const float* tp = (const float*)g_tp4[g];
    const float* kp = (const float*)g_kp4r[g];
    int stride = gridDim.x * blockDim.x;
    for (int idx = blockIdx.x * blockDim.x + threadIdx.x; idx < T; idx += stride) {
        int o = idx;
        float v;
        if (o < Np * 4) { v = praw[o]; }
        else {
            o -= Np * 4;
            if (o < Nn * 4) { v = praw[g_nsrc[g][o >> 2] * 4 + (o & 3)]; }
            else {
                o -= Nn * 4;
                if (o < Nt * 4) { v = traw[o]; }
                else {
                    o -= Nt * 4;
                    if (o < K) { v = (float)g_ti[g][o]; }
                    else {
                        o -= K;
                        if (o < K) { v = (float)g_pi[g][o]; }
                        else {
                            o -= K;
                            if (o < Kn) { v = (float)g_tin[g][o]; }
                            else {
                                o -= Kn;
                                if (o < Kn) { v = (float)g_pin[g][o]; }
                                else {
                                    o -= Kn;
                                    if (o < Np * 3) { v = pp[(o / 3) * 4 + o % 3]; }
                                    else {
                                        o -= Np * 3;
                                        if (o < Nn * 3) { v = kp[(o / 3) * 4 + o % 3]; }
                                        else { o -= Nn * 3; v = tp[(o / 3) * 4 + o % 3]; }
                                    }
                                }
                            }
                        }
                    }
                }
            }
        }
        out[base + idx] = v;
    }
}

// ---------------------------------------------------------------------------
// launch: 9 graph nodes
// ---------------------------------------------------------------------------
extern "C" void kernel_launch(void* const* d_in, const int* in_sizes, int n_in,
                              void* d_out, int out_size) {
    const float* pred = (const float*)d_in[0];
    const float* tgt  = (const float*)d_in[1];
    float* out = (float*)d_out;
    (void)in_sizes; (void)n_in; (void)out_size;

    dim3 wide(NCHUNK, NG);
    k_count<<<wide, 256>>>(pred, tgt);
    k_scan<<<NG, 1024>>>();
    k_scatter<<<wide, 256>>>(pred, tgt);
    k_res0<<<wide, 256>>>();
    k_sel<<<wide, 256>>>();
    k_rank<<<wide, 256>>>();
    k_match<<<wide, 256>>>();
    k_post<<<NG, 1024>>>();
    k_write<<<wide, 256>>>(out);
}